// round 4
// baseline (speedup 1.0000x reference)
#include <cuda_runtime.h>
#include <cstdint>

// Problem constants (fixed by the reference's setup_inputs)
#define NN 13          // nodes incl. driver
#define NR 12          // real (output) nodes
#define NB 4           // batch
#define NC 3           // channels
#define NH 256
#define NW 256
#define NE 37          // edges
#define KK 4           // kernel size
#define HW (NH*NW)     // 65536
#define PLANE (NC*HW)  // per (node,b) plane

// Scratch: sigmoid activations for all 13 nodes (~41 MB).
__device__ float g_act[(size_t)NN * NB * PLANE];

// ---------------------------------------------------------------------------
// Kernel 1: elementwise sigmoid, float4-vectorized
// ---------------------------------------------------------------------------
__global__ void sigmoid_kernel(const float* __restrict__ states, int n4) {
    int i = blockIdx.x * blockDim.x + threadIdx.x;
    if (i < n4) {
        float4 v = reinterpret_cast<const float4*>(states)[i];
        v.x = 1.f / (1.f + __expf(-v.x));
        v.y = 1.f / (1.f + __expf(-v.y));
        v.z = 1.f / (1.f + __expf(-v.z));
        v.w = 1.f / (1.f + __expf(-v.w));
        reinterpret_cast<float4*>(g_act)[i] = v;
    }
}

// ---------------------------------------------------------------------------
// Kernel 2: fused per-dest conv + segment mean, FFMA2 (f32x2) inner loop.
// Block = (dest node v, batch b, 32x32 tile), 256 threads.
// Thread (ty=tid>>3, tx=tid&7) computes a 1x4 output strip for all 3 couts,
// accumulated as two packed f32x2 pairs: (p0,p1) and (p2,p3).
// ---------------------------------------------------------------------------
#define TILE 32
#define HALO 35          // TILE + K - 1
#define SSTR 40          // smem row stride (floats): 160B -> 16B-aligned, conflict-free

typedef unsigned long long u64;

__device__ __forceinline__ u64 pk2(float lo, float hi) {
    u64 r; asm("mov.b64 %0, {%1, %2};" : "=l"(r) : "f"(lo), "f"(hi)); return r;
}
__device__ __forceinline__ void upk2(u64 v, float& lo, float& hi) {
    asm("mov.b64 {%0, %1}, %2;" : "=f"(lo), "=f"(hi) : "l"(v));
}
__device__ __forceinline__ void ffma2(u64& d, u64 a, u64 b) {
    asm("fma.rn.f32x2 %0, %1, %2, %0;" : "+l"(d) : "l"(a), "l"(b));
}

__global__ __launch_bounds__(256, 2)
void conv_kernel(const float* __restrict__ weights,   // [E][3][3][4][4]
                 const float* __restrict__ bias,      // [E][3]
                 const int*   __restrict__ edge_src,
                 const int*   __restrict__ edge_dst,
                 float*       __restrict__ out)       // [12][4][3][256][256]
{
    __shared__ float  sx[NC][HALO][SSTR];
    __shared__ float2 sw2[NC * NC * KK * KK];   // duplicated (w,w) pairs
    __shared__ float  sb[NC];
    __shared__ int    s_src[NE], s_dst[NE];

    const int tid = threadIdx.x;
    if (tid < NE) { s_src[tid] = edge_src[tid]; s_dst[tid] = edge_dst[tid]; }
    __syncthreads();

    const int v  = blockIdx.z;
    const int b  = blockIdx.y;
    const int h0 = (blockIdx.x >> 3) * TILE;
    const int w0 = (blockIdx.x & 7)  * TILE;

    const int ty = tid >> 3;        // 0..31 output row within tile
    const int tx = tid & 7;
    const int wl = tx * 4;          // output col start within tile

    u64   accLo[NC] = {0ull, 0ull, 0ull};   // bit pattern 0 == (0.f, 0.f)
    u64   accHi[NC] = {0ull, 0ull, 0ull};
    float bsum[NC]  = {0.f, 0.f, 0.f};

    int ne = 0;
    for (int e = 0; e < NE; e++) {
        if (s_dst[e] != v) continue;   // uniform across block
        ne++;
        const int src = s_src[e];
        const float* ap = g_act + ((size_t)src * NB + b) * PLANE;

        __syncthreads();   // protect sx/sw2 from previous edge's readers

        // Halo load: rows [h0-1, h0+34), loaded cols [w0-4, w0+36) as aligned
        // float4; smem col c corresponds to global col (w0-1)+c, so loaded
        // lane j of quad q maps to c = 4q-3+j. Because w0 and the image width
        // are multiples of 4, a quad is either fully in range or fully out.
        #pragma unroll 1
        for (int idx = tid; idx < NC * HALO * 10; idx += 256) {
            int cin = idx / (HALO * 10);
            int rem = idx - cin * (HALO * 10);
            int r   = rem / 10;
            int q   = rem - r * 10;
            int gh  = h0 - 1 + r;
            int gw  = w0 - 4 + q * 4;
            float4 vv = make_float4(0.f, 0.f, 0.f, 0.f);
            if ((unsigned)gh < (unsigned)NH && (unsigned)gw <= (unsigned)(NW - 4))
                vv = __ldg(reinterpret_cast<const float4*>(ap + cin * HW + gh * NW + gw));
            int c = q * 4 - 3;
            if ((unsigned)(c + 0) < (unsigned)HALO) sx[cin][r][c + 0] = vv.x;
            if ((unsigned)(c + 1) < (unsigned)HALO) sx[cin][r][c + 1] = vv.y;
            if ((unsigned)(c + 2) < (unsigned)HALO) sx[cin][r][c + 2] = vv.z;
            if ((unsigned)(c + 3) < (unsigned)HALO) sx[cin][r][c + 3] = vv.w;
        }
        if (tid < NC * NC * KK * KK) {
            float w = weights[e * (NC * NC * KK * KK) + tid];
            sw2[tid] = make_float2(w, w);
        }
        if (tid < NC) sb[tid] = bias[e * NC + tid];
        __syncthreads();

        #pragma unroll
        for (int cin = 0; cin < NC; cin++) {
            #pragma unroll
            for (int kh = 0; kh < KK; kh++) {
                const float* xr = &sx[cin][ty + kh][wl];
                float4 xa = *reinterpret_cast<const float4*>(xr);      // x0..x3
                float4 xb = *reinterpret_cast<const float4*>(xr + 4);  // x4..x7
                u64 P[6];
                P[0] = pk2(xa.x, xa.y);
                P[1] = pk2(xa.y, xa.z);
                P[2] = pk2(xa.z, xa.w);
                P[3] = pk2(xa.w, xb.x);
                P[4] = pk2(xb.x, xb.y);
                P[5] = pk2(xb.y, xb.z);
                #pragma unroll
                for (int kw = 0; kw < KK; kw++) {
                    #pragma unroll
                    for (int co = 0; co < NC; co++) {
                        u64 w2 = *reinterpret_cast<const u64*>(
                                     &sw2[co * 48 + cin * 16 + kh * 4 + kw]);
                        ffma2(accLo[co], P[kw],     w2);   // outputs p0,p1
                        ffma2(accHi[co], P[kw + 2], w2);   // outputs p2,p3
                    }
                }
            }
        }
        #pragma unroll
        for (int c = 0; c < NC; c++) bsum[c] += sb[c];
    }

    const float inv = 1.f / (float)ne;
    const size_t obase = ((size_t)v * NB + b) * PLANE
                       + (size_t)(h0 + ty) * NW + (w0 + wl);
    #pragma unroll
    for (int co = 0; co < NC; co++) {
        float a0, a1, a2, a3;
        upk2(accLo[co], a0, a1);
        upk2(accHi[co], a2, a3);
        float4 r;
        r.x = (a0 + bsum[co]) * inv;
        r.y = (a1 + bsum[co]) * inv;
        r.z = (a2 + bsum[co]) * inv;
        r.w = (a3 + bsum[co]) * inv;
        *reinterpret_cast<float4*>(out + obase + (size_t)co * HW) = r;
    }
}

// ---------------------------------------------------------------------------
extern "C" void kernel_launch(void* const* d_in, const int* in_sizes, int n_in,
                              void* d_out, int out_size)
{
    const float* states   = (const float*)d_in[0];  // [13,4,3,256,256]
    const float* weights  = (const float*)d_in[1];  // [37,3,3,4,4]
    const float* bias     = (const float*)d_in[2];  // [37,3]
    const int*   edge_src = (const int*)  d_in[3];  // [37]
    const int*   edge_dst = (const int*)  d_in[4];  // [37]
    float*       out      = (float*)      d_out;    // [12,4,3,256,256]

    const int n  = NN * NB * PLANE;          // divisible by 4
    const int n4 = n / 4;
    sigmoid_kernel<<<(n4 + 255) / 256, 256>>>(states, n4);

    dim3 grid(64, NB, NR);                   // 8x8 tiles, 4 batch, 12 nodes
    conv_kernel<<<grid, 256>>>(weights, bias, edge_src, edge_dst, out);
}